// round 14
// baseline (speedup 1.0000x reference)
#include <cuda_runtime.h>
#include <cuda_bf16.h>
#include <cuda_fp16.h>
#include <stdint.h>
#include <math.h>

#define BATCH   2
#define SEQ     2048
#define DM      1024
#define NH      16
#define HD      64
#define ROWS    (BATCH*SEQ)          // 4096
#define QKV_N   (3*DM)               // 3072
#define QSCALE  0.18033688011112042f // 0.125 * log2(e)
#define WBLK    ((DM*QKV_N/4 + DM*DM/4)/256)   // 4096 weight-convert blocks

typedef __nv_bfloat16  bf16;
typedef __nv_bfloat162 bf162;

// ---------------- scratch (device globals; no runtime allocation) ----------
__device__ bf16 g_h[ROWS * DM];           // rmsnorm output (bf16)
__device__ bf16 g_qkv[ROWS * QKV_N];      // Q,K bf16 (Q pre-scaled); V fp16
__device__ bf16 g_ctx[ROWS * DM];         // attention context (bf16)
__device__ bf16 g_wqkv_bf[DM * QKV_N];    // converted weights
__device__ bf16 g_wproj_bf[DM * DM];

// ---------------- asm helpers ------------------------------------------------
__device__ __forceinline__ unsigned s2u(const void* p) {
    return (unsigned)__cvta_generic_to_shared(p);
}
__device__ __forceinline__ void cp16(unsigned s, const void* g) {
    asm volatile("cp.async.cg.shared.global [%0], [%1], 16;" :: "r"(s), "l"(g));
}
#define CP_COMMIT() asm volatile("cp.async.commit_group;")
#define CP_WAIT(n)  asm volatile("cp.async.wait_group %0;" :: "n"(n))

__device__ __forceinline__ void ldx4(unsigned* r, unsigned a) {
    asm volatile("ldmatrix.sync.aligned.m8n8.x4.shared.b16 {%0,%1,%2,%3}, [%4];"
        : "=r"(r[0]), "=r"(r[1]), "=r"(r[2]), "=r"(r[3]) : "r"(a));
}
__device__ __forceinline__ void ldx4t(unsigned* r, unsigned a) {
    asm volatile("ldmatrix.sync.aligned.m8n8.x4.trans.shared.b16 {%0,%1,%2,%3}, [%4];"
        : "=r"(r[0]), "=r"(r[1]), "=r"(r[2]), "=r"(r[3]) : "r"(a));
}
__device__ __forceinline__ void mmabf(float* d, const unsigned* a,
                                      unsigned b0, unsigned b1) {
    asm volatile(
        "mma.sync.aligned.m16n8k16.row.col.f32.bf16.bf16.f32 "
        "{%0,%1,%2,%3}, {%4,%5,%6,%7}, {%8,%9}, {%0,%1,%2,%3};"
        : "+f"(d[0]), "+f"(d[1]), "+f"(d[2]), "+f"(d[3])
        : "r"(a[0]), "r"(a[1]), "r"(a[2]), "r"(a[3]), "r"(b0), "r"(b1));
}
__device__ __forceinline__ void mmaf16(float* d, const unsigned* a,
                                       unsigned b0, unsigned b1) {
    asm volatile(
        "mma.sync.aligned.m16n8k16.row.col.f32.f16.f16.f32 "
        "{%0,%1,%2,%3}, {%4,%5,%6,%7}, {%8,%9}, {%0,%1,%2,%3};"
        : "+f"(d[0]), "+f"(d[1]), "+f"(d[2]), "+f"(d[3])
        : "r"(a[0]), "r"(a[1]), "r"(a[2]), "r"(a[3]), "r"(b0), "r"(b1));
}
__device__ __forceinline__ unsigned pk2h(float a, float b) {
    __half2 h = __floats2half2_rn(a, b);
    return *(unsigned*)&h;
}
__device__ __forceinline__ unsigned h2ex2(unsigned x) {
    unsigned y;
    asm("ex2.approx.f16x2 %0, %1;" : "=r"(y) : "r"(x));
    return y;
}

// ---------------- kernel 0: prologue (weights->bf16  +  RMSNorm) -------------
__global__ void prologue_kernel(const float* __restrict__ x,
                                const float* __restrict__ nw,
                                const float* __restrict__ wq,
                                const float* __restrict__ wp) {
    __shared__ float sbuf[8];
    int t = threadIdx.x;
    if (blockIdx.x < WBLK) {
        // weight conversion
        int i = blockIdx.x * 256 + t;             // float4 index
        const int NQ = DM * QKV_N / 4;
        float4 v; bf16* dst;
        if (i < NQ) { v = ((const float4*)wq)[i]; dst = g_wqkv_bf + (size_t)i * 4; }
        else        { v = ((const float4*)wp)[i - NQ]; dst = g_wproj_bf + (size_t)(i - NQ) * 4; }
        bf162 a, b;
        a.x = __float2bfloat16(v.x); a.y = __float2bfloat16(v.y);
        b.x = __float2bfloat16(v.z); b.y = __float2bfloat16(v.w);
        *(bf162*)dst = a; *(bf162*)(dst + 2) = b;
        return;
    }
    // RMSNorm row
    int row = blockIdx.x - WBLK;
    const float4* xr = (const float4*)(x + (size_t)row * DM);
    float4 v = xr[t];
    float ss = v.x*v.x + v.y*v.y + v.z*v.z + v.w*v.w;
    #pragma unroll
    for (int o = 16; o > 0; o >>= 1) ss += __shfl_xor_sync(0xffffffffu, ss, o);
    if ((t & 31) == 0) sbuf[t >> 5] = ss;
    __syncthreads();
    float tot = sbuf[0]+sbuf[1]+sbuf[2]+sbuf[3]+sbuf[4]+sbuf[5]+sbuf[6]+sbuf[7];
    float inv = rsqrtf(tot * (1.0f / DM) + 1e-6f);
    float4 wv = ((const float4*)nw)[t];
    bf162 o1, o2;
    o1.x = __float2bfloat16(v.x * inv * wv.x);
    o1.y = __float2bfloat16(v.y * inv * wv.y);
    o2.x = __float2bfloat16(v.z * inv * wv.z);
    o2.y = __float2bfloat16(v.w * inv * wv.w);
    bf16* orow = g_h + (size_t)row * DM + t * 4;
    *(bf162*)orow = o1; *(bf162*)(orow + 2) = o2;
}

// ---------------- kernel 2/4: bf16 GEMM, 128x128x64, 2-stage, 1 bar/tile -----
// MODE 0: fp32 out + fp32 residual.
// MODE 2: 16-bit out; Q cols (<DM) bf16*QSCALE, K cols bf16, V cols (>=2DM) fp16.
template<int MODE>
__global__ __launch_bounds__(256)
void gemm_bf16(const bf16* __restrict__ A, const bf16* __restrict__ B,
               void* __restrict__ Cp, const float* __restrict__ res,
               int N, int K) {
    extern __shared__ bf16 smem[];
    bf16* As = smem;               // [2][128*64]
    bf16* Bs = smem + 2 * 8192;    // [2][64*128]
    unsigned sA = s2u(As), sB = s2u(Bs);
    int t = threadIdx.x, lane = t & 31, w = t >> 5;
    int g = lane >> 2, tig = lane & 3;
    int wm = w >> 1, wn = w & 1;
    int m0 = blockIdx.y * 128, n0 = blockIdx.x * 128;

    float acc[2][8][4];
    #pragma unroll
    for (int mt = 0; mt < 2; mt++)
        #pragma unroll
        for (int nt = 0; nt < 8; nt++)
            #pragma unroll
            for (int i = 0; i < 4; i++) acc[mt][nt][i] = 0.f;

    auto load_tile = [&](int st, int k0) {
        #pragma unroll
        for (int i = 0; i < 4; i++) {
            int idx = t + 256 * i;
            int r = idx >> 3, c = idx & 7;
            cp16(sA + (st * 8192 + r * 64 + ((c ^ (r & 7)) << 3)) * 2,
                 A + (size_t)(m0 + r) * K + k0 + c * 8);
        }
        #pragma unroll
        for (int i = 0; i < 4; i++) {
            int idx = t + 256 * i;
            int r = idx >> 4, c = idx & 15;
            cp16(sB + (st * 8192 + r * 128 + ((c ^ (r & 7)) << 3)) * 2,
                 B + (size_t)(k0 + r) * N + n0 + c * 8);
        }
        CP_COMMIT();
    };

    load_tile(0, 0);

    int NK = K / 64;
    for (int kt = 0; kt < NK; kt++) {
        CP_WAIT(0);                 // tile kt resident
        __syncthreads();            // stage (kt+1)&1 reads (iter kt-1) done
        if (kt + 1 < NK) load_tile((kt + 1) & 1, (kt + 1) * 64);
        unsigned bA = sA + (kt & 1) * 8192 * 2;
        unsigned bB = sB + (kt & 1) * 8192 * 2;
        #pragma unroll
        for (int ks = 0; ks < 4; ks++) {
            unsigned a[2][4];
            #pragma unroll
            for (int mt = 0; mt < 2; mt++) {
                int row = wm * 32 + mt * 16 + (lane & 15);
                int c = ks * 2 + (lane >> 4);
                ldx4(a[mt], bA + (row * 64 + ((c ^ (row & 7)) << 3)) * 2);
            }
            #pragma unroll
            for (int np = 0; np < 4; np++) {
                int krow = ks * 16 + (lane & 7) + ((lane >> 3) & 1) * 8;
                int c = wn * 8 + np * 2 + (lane >> 4);
                unsigned b[4];
                ldx4t(b, bB + (krow * 128 + ((c ^ (krow & 7)) << 3)) * 2);
                #pragma unroll
                for (int mt = 0; mt < 2; mt++) {
                    mmabf(acc[mt][2 * np],     a[mt], b[0], b[1]);
                    mmabf(acc[mt][2 * np + 1], a[mt], b[2], b[3]);
                }
            }
        }
    }

    float cs = (MODE == 2 && n0 < DM) ? QSCALE : 1.0f;
    bool v16 = (MODE == 2) && (n0 >= 2 * DM);   // V columns -> fp16

    #pragma unroll
    for (int mt = 0; mt < 2; mt++)
        #pragma unroll
        for (int half = 0; half < 2; half++) {
            int row = m0 + wm * 32 + mt * 16 + g + half * 8;
            #pragma unroll
            for (int nt = 0; nt < 8; nt++) {
                size_t idx = (size_t)row * N + n0 + wn * 64 + nt * 8 + 2 * tig;
                float v0 = acc[mt][nt][half * 2], v1 = acc[mt][nt][half * 2 + 1];
                if (MODE == 0) {
                    float2 r = *(const float2*)(res + idx);
                    *(float2*)((float*)Cp + idx) = make_float2(v0 + r.x, v1 + r.y);
                } else if (v16) {
                    unsigned o = pk2h(v0, v1);
                    *(unsigned*)((bf16*)Cp + idx) = o;
                } else {
                    bf162 o; o.x = __float2bfloat16(v0 * cs);
                             o.y = __float2bfloat16(v1 * cs);
                    *(bf162*)((bf16*)Cp + idx) = o;
                }
            }
        }
}

typedef void (*gemm_fn)(const bf16*, const bf16*, void*, const float*, int, int);

// ---------------- kernel 3: flash attention (v6) -----------------------------
// Block = 128 q-rows x one (b,h). 8 warps x 16 q-rows. KV tile 64, 2-stage,
// 1 barrier/tile. Q,K bf16 (Q pre-scaled, log2-domain shift-free softmax);
// V fp16. P = ex2.approx.f16x2 packed; PV MMA f16.
// l summed in fp32 from fp16 P (idle FMA pipe) -- no tensor-pipe ones-MMA.
__global__ __launch_bounds__(256, 2)
void attn_bf16() {
    extern __shared__ bf16 sm[];
    bf16* Qs = sm;                 // [128][64]
    bf16* Ks = Qs + 8192;          // [2][64][64]
    bf16* Vs = Ks + 8192;          // [2][64][64] (fp16 payload)
    unsigned sQ = s2u(Qs), sK = s2u(Ks), sV = s2u(Vs);

    int t = threadIdx.x, lane = t & 31, w = t >> 5;
    int g = lane >> 2, tig = lane & 3;
    int rbase = w * 16;
    int q0 = blockIdx.x * 128;
    int bh = blockIdx.y, b = bh >> 4, h = bh & 15;
    const bf16* qb = g_qkv + (size_t)b * SEQ * QKV_N + h * HD;
    const bf16* kb = qb + DM;
    const bf16* vb = qb + 2 * DM;   // fp16 payload, same element size

    #pragma unroll
    for (int i = 0; i < 4; i++) {
        int idx = t + 256 * i;
        int r = idx >> 3, c = idx & 7;
        cp16(sQ + (r * 64 + ((c ^ (r & 7)) << 3)) * 2,
             qb + (size_t)(q0 + r) * QKV_N + c * 8);
    }
    auto loadKV = [&](int st, int k0) {
        #pragma unroll
        for (int i = 0; i < 2; i++) {
            int idx = t + 256 * i;
            int r = idx >> 3, c = idx & 7;
            unsigned off = (st * 4096 + r * 64 + ((c ^ (r & 7)) << 3)) * 2;
            cp16(sK + off, kb + (size_t)(k0 + r) * QKV_N + c * 8);
            cp16(sV + off, vb + (size_t)(k0 + r) * QKV_N + c * 8);
        }
        CP_COMMIT();
    };
    loadKV(0, 0);                   // Q + KV0 in one group

    CP_WAIT(0);                     // Q + KV0 resident
    __syncthreads();
    unsigned qa[4][4];
    #pragma unroll
    for (int ks = 0; ks < 4; ks++) {
        int row = rbase + (lane & 15);
        int c = ks * 2 + (lane >> 4);
        ldx4(qa[ks], sQ + (row * 64 + ((c ^ (row & 7)) << 3)) * 2);
    }

    float oacc[8][4];
    #pragma unroll
    for (int nt = 0; nt < 8; nt++)
        #pragma unroll
        for (int i = 0; i < 4; i++) oacc[nt][i] = 0.f;
    float l_lo = 0.f, l_hi = 0.f;   // per-thread partial row sums (fp32)

    const int NT = SEQ / 64;
    for (int kt = 0; kt < NT; kt++) {
        if (kt > 0) {
            CP_WAIT(0);             // tile kt resident
            __syncthreads();        // stage (kt+1)&1 reads (iter kt-1) done
        }
        if (kt + 1 < NT) loadKV((kt + 1) & 1, (kt + 1) * 64);
        unsigned bK = sK + (kt & 1) * 4096 * 2;
        unsigned bV = sV + (kt & 1) * 4096 * 2;

        // S = Q K^T (log2-domain scores; Q pre-scaled)
        float s[8][4];
        #pragma unroll
        for (int nt = 0; nt < 8; nt++)
            #pragma unroll
            for (int i = 0; i < 4; i++) s[nt][i] = 0.f;
        #pragma unroll
        for (int ks = 0; ks < 4; ks++) {
            #pragma unroll
            for (int np = 0; np < 4; np++) {
                int row = np * 16 + (lane & 7) + ((lane >> 4) & 1) * 8;
                int c = ks * 2 + ((lane >> 3) & 1);
                unsigned kbf[4];
                ldx4(kbf, bK + (row * 64 + ((c ^ (row & 7)) << 3)) * 2);
                mmabf(s[2 * np],     qa[ks], kbf[0], kbf[1]);
                mmabf(s[2 * np + 1], qa[ks], kbf[2], kbf[3]);
            }
        }

        // P = 2^s, packed fp16x2; l accumulated in fp32 (FMA pipe)
        unsigned pp[8][2];
        #pragma unroll
        for (int nt = 0; nt < 8; nt++) {
            unsigned plo = h2ex2(pk2h(s[nt][0], s[nt][1]));   // rows g
            unsigned phi = h2ex2(pk2h(s[nt][2], s[nt][3]));   // rows g+8
            pp[nt][0] = plo;
            pp[nt][1] = phi;
            float2 flo = __half22float2(*(__half2*)&plo);
            float2 fhi = __half22float2(*(__half2*)&phi);
            l_lo += flo.x + flo.y;
            l_hi += fhi.x + fhi.y;
        }

        // O += P @ V (f16 MMA)
        #pragma unroll
        for (int ks = 0; ks < 4; ks++) {
            unsigned pa[4];
            pa[0] = pp[2 * ks][0];
            pa[1] = pp[2 * ks][1];
            pa[2] = pp[2 * ks + 1][0];
            pa[3] = pp[2 * ks + 1][1];
            #pragma unroll
            for (int np = 0; np < 4; np++) {
                int krow = ks * 16 + (lane & 7) + ((lane >> 3) & 1) * 8;
                int c = np * 2 + (lane >> 4);
                unsigned vbf[4];
                ldx4t(vbf, bV + (krow * 64 + ((c ^ (krow & 7)) << 3)) * 2);
                mmaf16(oacc[2 * np],     pa, vbf[0], vbf[1]);
                mmaf16(oacc[2 * np + 1], pa, vbf[2], vbf[3]);
            }
        }
    }

    // final row-sum reduction across the quad (cols spread over 4 lanes)
    l_lo += __shfl_xor_sync(0xffffffffu, l_lo, 1);
    l_lo += __shfl_xor_sync(0xffffffffu, l_lo, 2);
    l_hi += __shfl_xor_sync(0xffffffffu, l_hi, 1);
    l_hi += __shfl_xor_sync(0xffffffffu, l_hi, 2);

    // epilogue -> g_ctx (bf16)
    float il_lo = 1.f / l_lo, il_hi = 1.f / l_hi;
    size_t row_lo = (size_t)(b * SEQ + q0 + rbase + g);
    #pragma unroll
    for (int nt = 0; nt < 8; nt++) {
        size_t cidx = row_lo * DM + h * HD + nt * 8 + 2 * tig;
        bf162 o0; o0.x = __float2bfloat16(oacc[nt][0] * il_lo);
                  o0.y = __float2bfloat16(oacc[nt][1] * il_lo);
        *(bf162*)(g_ctx + cidx) = o0;
        bf162 o1; o1.x = __float2bfloat16(oacc[nt][2] * il_hi);
                  o1.y = __float2bfloat16(oacc[nt][3] * il_hi);
        *(bf162*)(g_ctx + cidx + 8 * DM) = o1;
    }
}

// ---------------- launch -----------------------------------------------------
extern "C" void kernel_launch(void* const* d_in, const int* in_sizes, int n_in,
                              void* d_out, int out_size) {
    const float* x      = (const float*)d_in[0];
    const float* norm_w = (const float*)d_in[1];
    const float* w_qkv  = (const float*)d_in[2];
    const float* w_proj = (const float*)d_in[3];
    float* out = (float*)d_out;

    bf16 *ph, *pqkv, *pctx, *pwq, *pwp;
    cudaGetSymbolAddress((void**)&ph,   g_h);
    cudaGetSymbolAddress((void**)&pqkv, g_qkv);
    cudaGetSymbolAddress((void**)&pctx, g_ctx);
    cudaGetSymbolAddress((void**)&pwq,  g_wqkv_bf);
    cudaGetSymbolAddress((void**)&pwp,  g_wproj_bf);

    gemm_fn gemm_qkv = gemm_bf16<2>;   // Q bf16*QSCALE, K bf16, V fp16
    gemm_fn gemm_out = gemm_bf16<0>;   // fp32 out + residual

    // 0+1) weights->bf16 and RMSNorm in one launch
    prologue_kernel<<<WBLK + ROWS, 256>>>(x, norm_w, w_qkv, w_proj);

    const int gemm_smem = 2 * (8192 + 8192) * (int)sizeof(bf16);   // 64 KB
    cudaFuncSetAttribute(gemm_qkv,
                         cudaFuncAttributeMaxDynamicSharedMemorySize, gemm_smem);
    cudaFuncSetAttribute(gemm_out,
                         cudaFuncAttributeMaxDynamicSharedMemorySize, gemm_smem);

    // 2) QKV projection
    gemm_qkv<<<dim3(QKV_N / 128, ROWS / 128), 256, gemm_smem>>>(
        ph, pwq, pqkv, nullptr, QKV_N, DM);

    // 3) flash attention (48 KB smem -> 2 CTAs/SM)
    const int attn_smem = (8192 + 8192 + 8192) * (int)sizeof(bf16);
    cudaFuncSetAttribute(attn_bf16,
                         cudaFuncAttributeMaxDynamicSharedMemorySize, attn_smem);
    attn_bf16<<<dim3(SEQ / 128, BATCH * NH), 256, attn_smem>>>();

    // 4) out projection + residual (fp32 out)
    gemm_out<<<dim3(DM / 128, ROWS / 128), 256, gemm_smem>>>(
        pctx, pwp, out, x, DM, DM);
}

// round 16
// speedup vs baseline: 1.0375x; 1.0375x over previous
#include <cuda_runtime.h>
#include <cuda_bf16.h>
#include <cuda_fp16.h>
#include <stdint.h>
#include <math.h>

#define BATCH   2
#define SEQ     2048
#define DM      1024
#define NH      16
#define HD      64
#define ROWS    (BATCH*SEQ)          // 4096
#define QKV_N   (3*DM)               // 3072
#define QSCALE  0.18033688011112042f // 0.125 * log2(e)
#define ONES2   0x3C003C00u          // fp16x2 (1.0, 1.0)
#define WBLK    ((DM*QKV_N/4 + DM*DM/4)/256)   // 4096 weight-convert blocks

typedef __nv_bfloat16  bf16;
typedef __nv_bfloat162 bf162;

// ---------------- scratch (device globals; no runtime allocation) ----------
__device__ bf16 g_h[ROWS * DM];           // rmsnorm output (bf16)
__device__ bf16 g_qkv[ROWS * QKV_N];      // Q,K bf16 (Q pre-scaled); V fp16
__device__ bf16 g_ctx[ROWS * DM];         // attention context (bf16)
__device__ bf16 g_wqkv_bf[DM * QKV_N];    // converted weights
__device__ bf16 g_wproj_bf[DM * DM];

// ---------------- asm helpers ------------------------------------------------
__device__ __forceinline__ unsigned s2u(const void* p) {
    return (unsigned)__cvta_generic_to_shared(p);
}
__device__ __forceinline__ void cp16(unsigned s, const void* g) {
    asm volatile("cp.async.cg.shared.global [%0], [%1], 16;" :: "r"(s), "l"(g));
}
#define CP_COMMIT() asm volatile("cp.async.commit_group;")
#define CP_WAIT(n)  asm volatile("cp.async.wait_group %0;" :: "n"(n))

__device__ __forceinline__ void ldx4(unsigned* r, unsigned a) {
    asm volatile("ldmatrix.sync.aligned.m8n8.x4.shared.b16 {%0,%1,%2,%3}, [%4];"
        : "=r"(r[0]), "=r"(r[1]), "=r"(r[2]), "=r"(r[3]) : "r"(a));
}
__device__ __forceinline__ void ldx4t(unsigned* r, unsigned a) {
    asm volatile("ldmatrix.sync.aligned.m8n8.x4.trans.shared.b16 {%0,%1,%2,%3}, [%4];"
        : "=r"(r[0]), "=r"(r[1]), "=r"(r[2]), "=r"(r[3]) : "r"(a));
}
__device__ __forceinline__ void mmabf(float* d, const unsigned* a,
                                      unsigned b0, unsigned b1) {
    asm volatile(
        "mma.sync.aligned.m16n8k16.row.col.f32.bf16.bf16.f32 "
        "{%0,%1,%2,%3}, {%4,%5,%6,%7}, {%8,%9}, {%0,%1,%2,%3};"
        : "+f"(d[0]), "+f"(d[1]), "+f"(d[2]), "+f"(d[3])
        : "r"(a[0]), "r"(a[1]), "r"(a[2]), "r"(a[3]), "r"(b0), "r"(b1));
}
__device__ __forceinline__ void mmaf16(float* d, const unsigned* a,
                                       unsigned b0, unsigned b1) {
    asm volatile(
        "mma.sync.aligned.m16n8k16.row.col.f32.f16.f16.f32 "
        "{%0,%1,%2,%3}, {%4,%5,%6,%7}, {%8,%9}, {%0,%1,%2,%3};"
        : "+f"(d[0]), "+f"(d[1]), "+f"(d[2]), "+f"(d[3])
        : "r"(a[0]), "r"(a[1]), "r"(a[2]), "r"(a[3]), "r"(b0), "r"(b1));
}
__device__ __forceinline__ unsigned pk2h(float a, float b) {
    __half2 h = __floats2half2_rn(a, b);
    return *(unsigned*)&h;
}
__device__ __forceinline__ unsigned h2ex2(unsigned x) {
    unsigned y;
    asm("ex2.approx.f16x2 %0, %1;" : "=r"(y) : "r"(x));
    return y;
}

// ---------------- kernel 0: prologue (weights->bf16  +  RMSNorm) -------------
__global__ void prologue_kernel(const float* __restrict__ x,
                                const float* __restrict__ nw,
                                const float* __restrict__ wq,
                                const float* __restrict__ wp) {
    __shared__ float sbuf[8];
    int t = threadIdx.x;
    if (blockIdx.x < WBLK) {
        // weight conversion
        int i = blockIdx.x * 256 + t;             // float4 index
        const int NQ = DM * QKV_N / 4;
        float4 v; bf16* dst;
        if (i < NQ) { v = ((const float4*)wq)[i]; dst = g_wqkv_bf + (size_t)i * 4; }
        else        { v = ((const float4*)wp)[i - NQ]; dst = g_wproj_bf + (size_t)(i - NQ) * 4; }
        bf162 a, b;
        a.x = __float2bfloat16(v.x); a.y = __float2bfloat16(v.y);
        b.x = __float2bfloat16(v.z); b.y = __float2bfloat16(v.w);
        *(bf162*)dst = a; *(bf162*)(dst + 2) = b;
        return;
    }
    // RMSNorm row
    int row = blockIdx.x - WBLK;
    const float4* xr = (const float4*)(x + (size_t)row * DM);
    float4 v = xr[t];
    float ss = v.x*v.x + v.y*v.y + v.z*v.z + v.w*v.w;
    #pragma unroll
    for (int o = 16; o > 0; o >>= 1) ss += __shfl_xor_sync(0xffffffffu, ss, o);
    if ((t & 31) == 0) sbuf[t >> 5] = ss;
    __syncthreads();
    float tot = sbuf[0]+sbuf[1]+sbuf[2]+sbuf[3]+sbuf[4]+sbuf[5]+sbuf[6]+sbuf[7];
    float inv = rsqrtf(tot * (1.0f / DM) + 1e-6f);
    float4 wv = ((const float4*)nw)[t];
    bf162 o1, o2;
    o1.x = __float2bfloat16(v.x * inv * wv.x);
    o1.y = __float2bfloat16(v.y * inv * wv.y);
    o2.x = __float2bfloat16(v.z * inv * wv.z);
    o2.y = __float2bfloat16(v.w * inv * wv.w);
    bf16* orow = g_h + (size_t)row * DM + t * 4;
    *(bf162*)orow = o1; *(bf162*)(orow + 2) = o2;
}

// ---------------- kernel 2/4: bf16 GEMM, 128x128x64, 2-stage, 1 bar/tile -----
// MODE 0: fp32 out + fp32 residual.
// MODE 2: 16-bit out; Q cols (<DM) bf16*QSCALE, K cols bf16, V cols (>=2DM) fp16.
template<int MODE>
__global__ __launch_bounds__(256)
void gemm_bf16(const bf16* __restrict__ A, const bf16* __restrict__ B,
               void* __restrict__ Cp, const float* __restrict__ res,
               int N, int K) {
    extern __shared__ bf16 smem[];
    bf16* As = smem;               // [2][128*64]
    bf16* Bs = smem + 2 * 8192;    // [2][64*128]
    unsigned sA = s2u(As), sB = s2u(Bs);
    int t = threadIdx.x, lane = t & 31, w = t >> 5;
    int g = lane >> 2, tig = lane & 3;
    int wm = w >> 1, wn = w & 1;
    int m0 = blockIdx.y * 128, n0 = blockIdx.x * 128;

    float acc[2][8][4];
    #pragma unroll
    for (int mt = 0; mt < 2; mt++)
        #pragma unroll
        for (int nt = 0; nt < 8; nt++)
            #pragma unroll
            for (int i = 0; i < 4; i++) acc[mt][nt][i] = 0.f;

    auto load_tile = [&](int st, int k0) {
        #pragma unroll
        for (int i = 0; i < 4; i++) {
            int idx = t + 256 * i;
            int r = idx >> 3, c = idx & 7;
            cp16(sA + (st * 8192 + r * 64 + ((c ^ (r & 7)) << 3)) * 2,
                 A + (size_t)(m0 + r) * K + k0 + c * 8);
        }
        #pragma unroll
        for (int i = 0; i < 4; i++) {
            int idx = t + 256 * i;
            int r = idx >> 4, c = idx & 15;
            cp16(sB + (st * 8192 + r * 128 + ((c ^ (r & 7)) << 3)) * 2,
                 B + (size_t)(k0 + r) * N + n0 + c * 8);
        }
        CP_COMMIT();
    };

    load_tile(0, 0);

    int NK = K / 64;
    for (int kt = 0; kt < NK; kt++) {
        CP_WAIT(0);                 // tile kt resident
        __syncthreads();            // stage (kt+1)&1 reads (iter kt-1) done
        if (kt + 1 < NK) load_tile((kt + 1) & 1, (kt + 1) * 64);
        unsigned bA = sA + (kt & 1) * 8192 * 2;
        unsigned bB = sB + (kt & 1) * 8192 * 2;
        #pragma unroll
        for (int ks = 0; ks < 4; ks++) {
            unsigned a[2][4];
            #pragma unroll
            for (int mt = 0; mt < 2; mt++) {
                int row = wm * 32 + mt * 16 + (lane & 15);
                int c = ks * 2 + (lane >> 4);
                ldx4(a[mt], bA + (row * 64 + ((c ^ (row & 7)) << 3)) * 2);
            }
            #pragma unroll
            for (int np = 0; np < 4; np++) {
                int krow = ks * 16 + (lane & 7) + ((lane >> 3) & 1) * 8;
                int c = wn * 8 + np * 2 + (lane >> 4);
                unsigned b[4];
                ldx4t(b, bB + (krow * 128 + ((c ^ (krow & 7)) << 3)) * 2);
                #pragma unroll
                for (int mt = 0; mt < 2; mt++) {
                    mmabf(acc[mt][2 * np],     a[mt], b[0], b[1]);
                    mmabf(acc[mt][2 * np + 1], a[mt], b[2], b[3]);
                }
            }
        }
    }

    float cs = (MODE == 2 && n0 < DM) ? QSCALE : 1.0f;
    bool v16 = (MODE == 2) && (n0 >= 2 * DM);   // V columns -> fp16

    #pragma unroll
    for (int mt = 0; mt < 2; mt++)
        #pragma unroll
        for (int half = 0; half < 2; half++) {
            int row = m0 + wm * 32 + mt * 16 + g + half * 8;
            #pragma unroll
            for (int nt = 0; nt < 8; nt++) {
                size_t idx = (size_t)row * N + n0 + wn * 64 + nt * 8 + 2 * tig;
                float v0 = acc[mt][nt][half * 2], v1 = acc[mt][nt][half * 2 + 1];
                if (MODE == 0) {
                    float2 r = *(const float2*)(res + idx);
                    *(float2*)((float*)Cp + idx) = make_float2(v0 + r.x, v1 + r.y);
                } else if (v16) {
                    unsigned o = pk2h(v0, v1);
                    *(unsigned*)((bf16*)Cp + idx) = o;
                } else {
                    bf162 o; o.x = __float2bfloat16(v0 * cs);
                             o.y = __float2bfloat16(v1 * cs);
                    *(bf162*)((bf16*)Cp + idx) = o;
                }
            }
        }
}

typedef void (*gemm_fn)(const bf16*, const bf16*, void*, const float*, int, int);

// ---------------- kernel 3: flash attention (v7: 32 q-rows/warp) -------------
// Block = 256 q-rows x one (b,h). 8 warps x 32 q-rows (2 m-frags each).
// KV tile 64, 2-stage, 1 barrier/tile. K/V fragments loaded ONCE per tile and
// fed to both m-frags -> LDSM per MMA halved vs 16-row warps (L1 was co-bound
// with tensor at ~61%). 1 CTA/SM (regs ~200), 8 warps.
// Q,K bf16 (Q pre-scaled, log2 softmax); V fp16; P = ex2.f16x2; l = ones-MMA.
__global__ __launch_bounds__(256, 1)
void attn_bf16() {
    extern __shared__ bf16 sm[];
    bf16* Qs = sm;                 // [256][64]
    bf16* Ks = Qs + 16384;         // [2][64][64]
    bf16* Vs = Ks + 8192;          // [2][64][64] (fp16 payload)
    unsigned sQ = s2u(Qs), sK = s2u(Ks), sV = s2u(Vs);

    int t = threadIdx.x, lane = t & 31, w = t >> 5;
    int g = lane >> 2, tig = lane & 3;
    int rbase = w * 32;
    int q0 = blockIdx.x * 256;
    int bh = blockIdx.y, b = bh >> 4, h = bh & 15;
    const bf16* qb = g_qkv + (size_t)b * SEQ * QKV_N + h * HD;
    const bf16* kb = qb + DM;
    const bf16* vb = qb + 2 * DM;   // fp16 payload, same element size

    // Q tile load: 256 rows x 8 16B-chunks
    #pragma unroll
    for (int i = 0; i < 8; i++) {
        int idx = t + 256 * i;
        int r = idx >> 3, c = idx & 7;
        cp16(sQ + (r * 64 + ((c ^ (r & 7)) << 3)) * 2,
             qb + (size_t)(q0 + r) * QKV_N + c * 8);
    }
    auto loadKV = [&](int st, int k0) {
        #pragma unroll
        for (int i = 0; i < 2; i++) {
            int idx = t + 256 * i;
            int r = idx >> 3, c = idx & 7;
            unsigned off = (st * 4096 + r * 64 + ((c ^ (r & 7)) << 3)) * 2;
            cp16(sK + off, kb + (size_t)(k0 + r) * QKV_N + c * 8);
            cp16(sV + off, vb + (size_t)(k0 + r) * QKV_N + c * 8);
        }
        CP_COMMIT();
    };
    loadKV(0, 0);                   // Q + KV0 in one group

    CP_WAIT(0);                     // Q + KV0 resident
    __syncthreads();
    unsigned qa[2][4][4];
    #pragma unroll
    for (int mt = 0; mt < 2; mt++)
        #pragma unroll
        for (int ks = 0; ks < 4; ks++) {
            int row = rbase + mt * 16 + (lane & 15);
            int c = ks * 2 + (lane >> 4);
            ldx4(qa[mt][ks], sQ + (row * 64 + ((c ^ (row & 7)) << 3)) * 2);
        }

    float oacc[2][8][4];
    #pragma unroll
    for (int mt = 0; mt < 2; mt++)
        #pragma unroll
        for (int nt = 0; nt < 8; nt++)
            #pragma unroll
            for (int i = 0; i < 4; i++) oacc[mt][nt][i] = 0.f;
    float lacc[2][4];
    #pragma unroll
    for (int mt = 0; mt < 2; mt++)
        #pragma unroll
        for (int i = 0; i < 4; i++) lacc[mt][i] = 0.f;

    const int NT = SEQ / 64;
    for (int kt = 0; kt < NT; kt++) {
        if (kt > 0) {
            CP_WAIT(0);             // tile kt resident
            __syncthreads();        // stage (kt+1)&1 reads (iter kt-1) done
        }
        if (kt + 1 < NT) loadKV((kt + 1) & 1, (kt + 1) * 64);
        unsigned bK = sK + (kt & 1) * 4096 * 2;
        unsigned bV = sV + (kt & 1) * 4096 * 2;

        // S = Q K^T; K fragment loaded once, used by both m-frags
        float s[2][8][4];
        #pragma unroll
        for (int mt = 0; mt < 2; mt++)
            #pragma unroll
            for (int nt = 0; nt < 8; nt++)
                #pragma unroll
                for (int i = 0; i < 4; i++) s[mt][nt][i] = 0.f;
        #pragma unroll
        for (int ks = 0; ks < 4; ks++) {
            #pragma unroll
            for (int np = 0; np < 4; np++) {
                int row = np * 16 + (lane & 7) + ((lane >> 4) & 1) * 8;
                int c = ks * 2 + ((lane >> 3) & 1);
                unsigned kbf[4];
                ldx4(kbf, bK + (row * 64 + ((c ^ (row & 7)) << 3)) * 2);
                #pragma unroll
                for (int mt = 0; mt < 2; mt++) {
                    mmabf(s[mt][2 * np],     qa[mt][ks], kbf[0], kbf[1]);
                    mmabf(s[mt][2 * np + 1], qa[mt][ks], kbf[2], kbf[3]);
                }
            }
        }

        // P = 2^s, packed fp16x2 (one MUFU op per pair)
        unsigned pp[2][8][2];
        #pragma unroll
        for (int mt = 0; mt < 2; mt++)
            #pragma unroll
            for (int nt = 0; nt < 8; nt++) {
                pp[mt][nt][0] = h2ex2(pk2h(s[mt][nt][0], s[mt][nt][1]));
                pp[mt][nt][1] = h2ex2(pk2h(s[mt][nt][2], s[mt][nt][3]));
            }

        // O += P @ V; V fragment loaded once, used by both m-frags; l ones-MMA
        #pragma unroll
        for (int ks = 0; ks < 4; ks++) {
            unsigned pa[2][4];
            #pragma unroll
            for (int mt = 0; mt < 2; mt++) {
                pa[mt][0] = pp[mt][2 * ks][0];
                pa[mt][1] = pp[mt][2 * ks][1];
                pa[mt][2] = pp[mt][2 * ks + 1][0];
                pa[mt][3] = pp[mt][2 * ks + 1][1];
                mmaf16(lacc[mt], pa[mt], ONES2, ONES2);
            }
            #pragma unroll
            for (int np = 0; np < 4; np++) {
                int krow = ks * 16 + (lane & 7) + ((lane >> 3) & 1) * 8;
                int c = np * 2 + (lane >> 4);
                unsigned vbf[4];
                ldx4t(vbf, bV + (krow * 64 + ((c ^ (krow & 7)) << 3)) * 2);
                #pragma unroll
                for (int mt = 0; mt < 2; mt++) {
                    mmaf16(oacc[mt][2 * np],     pa[mt], vbf[0], vbf[1]);
                    mmaf16(oacc[mt][2 * np + 1], pa[mt], vbf[2], vbf[3]);
                }
            }
        }
    }

    // epilogue -> g_ctx (bf16); l exact from ones-MMA (all quad lanes agree)
    #pragma unroll
    for (int mt = 0; mt < 2; mt++) {
        float il_lo = 1.f / lacc[mt][0], il_hi = 1.f / lacc[mt][2];
        size_t row_lo = (size_t)(b * SEQ + q0 + rbase + mt * 16 + g);
        #pragma unroll
        for (int nt = 0; nt < 8; nt++) {
            size_t cidx = row_lo * DM + h * HD + nt * 8 + 2 * tig;
            bf162 o0; o0.x = __float2bfloat16(oacc[mt][nt][0] * il_lo);
                      o0.y = __float2bfloat16(oacc[mt][nt][1] * il_lo);
            *(bf162*)(g_ctx + cidx) = o0;
            bf162 o1; o1.x = __float2bfloat16(oacc[mt][nt][2] * il_hi);
                      o1.y = __float2bfloat16(oacc[mt][nt][3] * il_hi);
            *(bf162*)(g_ctx + cidx + 8 * DM) = o1;
        }
    }
}

// ---------------- launch -----------------------------------------------------
extern "C" void kernel_launch(void* const* d_in, const int* in_sizes, int n_in,
                              void* d_out, int out_size) {
    const float* x      = (const float*)d_in[0];
    const float* norm_w = (const float*)d_in[1];
    const float* w_qkv  = (const float*)d_in[2];
    const float* w_proj = (const float*)d_in[3];
    float* out = (float*)d_out;

    bf16 *ph, *pqkv, *pctx, *pwq, *pwp;
    cudaGetSymbolAddress((void**)&ph,   g_h);
    cudaGetSymbolAddress((void**)&pqkv, g_qkv);
    cudaGetSymbolAddress((void**)&pctx, g_ctx);
    cudaGetSymbolAddress((void**)&pwq,  g_wqkv_bf);
    cudaGetSymbolAddress((void**)&pwp,  g_wproj_bf);

    gemm_fn gemm_qkv = gemm_bf16<2>;   // Q bf16*QSCALE, K bf16, V fp16
    gemm_fn gemm_out = gemm_bf16<0>;   // fp32 out + residual

    // 0+1) weights->bf16 and RMSNorm in one launch
    prologue_kernel<<<WBLK + ROWS, 256>>>(x, norm_w, w_qkv, w_proj);

    const int gemm_smem = 2 * (8192 + 8192) * (int)sizeof(bf16);   // 64 KB
    cudaFuncSetAttribute(gemm_qkv,
                         cudaFuncAttributeMaxDynamicSharedMemorySize, gemm_smem);
    cudaFuncSetAttribute(gemm_out,
                         cudaFuncAttributeMaxDynamicSharedMemorySize, gemm_smem);

    // 2) QKV projection
    gemm_qkv<<<dim3(QKV_N / 128, ROWS / 128), 256, gemm_smem>>>(
        ph, pwq, pqkv, nullptr, QKV_N, DM);

    // 3) flash attention (64 KB smem, 1 CTA/SM, 256 q-rows/CTA)
    const int attn_smem = (16384 + 8192 + 8192) * (int)sizeof(bf16);
    cudaFuncSetAttribute(attn_bf16,
                         cudaFuncAttributeMaxDynamicSharedMemorySize, attn_smem);
    attn_bf16<<<dim3(SEQ / 256, BATCH * NH), 256, attn_smem>>>();

    // 4) out projection + residual (fp32 out)
    gemm_out<<<dim3(DM / 128, ROWS / 128), 256, gemm_smem>>>(
        pctx, pwp, out, x, DM, DM);
}